// round 2
// baseline (speedup 1.0000x reference)
#include <cuda_runtime.h>
#include <cuda_bf16.h>
#include <cstdint>

#define BATCH 8192
#define DIM   2048
#define EPSV  1e-8f
#define MARGINV 0.2f

static constexpr int THREADS = 256;
static constexpr int ROW_F4  = DIM / 4;   // 512

__device__ float2 g_loss[BATCH];
__device__ int    g_is32;   // 1 if cand arrays are int32, 0 if int64

__device__ __forceinline__ float dot4(float4 a, float4 b) {
    return a.x * b.x + a.y * b.y + a.z * b.z + a.w * b.w;
}

// Probe index dtype: for int64 data (values < 8192) all odd 32-bit words are 0.
// For int32 data the odd words are random candidate ids (nonzero w.p. ~1).
__global__ __launch_bounds__(1024)
void detect_dtype(const unsigned* __restrict__ c0,
                  const unsigned* __restrict__ c1) {
    unsigned any = 0;
    // 16384 words is safe under both layouts (int32: whole buffer; int64: half)
    for (int i = threadIdx.x * 2 + 1; i < 16384; i += 2048) {
        any |= c0[i] | c1[i];
    }
    #pragma unroll
    for (int off = 16; off > 0; off >>= 1)
        any |= __shfl_xor_sync(0xFFFFFFFFu, any, off);
    __shared__ unsigned s[32];
    const int lane = threadIdx.x & 31, warp = threadIdx.x >> 5;
    if (lane == 0) s[warp] = any;
    __syncthreads();
    if (threadIdx.x == 0) {
        unsigned r = 0;
        #pragma unroll
        for (int w = 0; w < 32; w++) r |= s[w];
        g_is32 = (r != 0) ? 1 : 0;
    }
}

__device__ __forceinline__ void load_pair(const void* cand, int row,
                                          int is32, int& c0, int& c1) {
    if (is32) {
        const int* p = (const int*)cand;
        c0 = p[2 * row];
        c1 = p[2 * row + 1];
    } else {
        const long long* p = (const long long*)cand;
        c0 = (int)p[2 * row];
        c1 = (int)p[2 * row + 1];
    }
}

__global__ __launch_bounds__(THREADS)
void contrastive_main(const float4* __restrict__ img,
                      const float4* __restrict__ txt,
                      const void* __restrict__ cand_img,
                      const void* __restrict__ cand_txt,
                      float* __restrict__ out) {
    const int row = blockIdx.x;
    const int t   = threadIdx.x;
    const int is32 = g_is32;

    int a0, a1, b0, b1;
    load_pair(cand_img, row, is32, a0, a1);
    load_pair(cand_txt, row, is32, b0, b1);
    // clamp defensively (never triggers on valid data)
    a0 &= (BATCH - 1); a1 &= (BATCH - 1); b0 &= (BATCH - 1); b1 &= (BATCH - 1);

    const float4* ir = img + (size_t)row * ROW_F4;
    const float4* tr = txt + (size_t)row * ROW_F4;

    float4 iv0 = ir[t], iv1 = ir[t + THREADS];
    float4 tv0 = tr[t], tv1 = tr[t + THREADS];

    float acc[11];
    acc[0] = dot4(iv0, iv0) + dot4(iv1, iv1);          // ||img||^2
    acc[1] = dot4(tv0, tv0) + dot4(tv1, tv1);          // ||text||^2
    acc[2] = dot4(iv0, tv0) + dot4(iv1, tv1);          // img.text

    {   // img candidates (anchor = text) -> t2i side
        const float4* g = img + (size_t)a0 * ROW_F4;
        float4 g0 = g[t], g1 = g[t + THREADS];
        acc[3] = dot4(tv0, g0) + dot4(tv1, g1);
        acc[4] = dot4(g0, g0) + dot4(g1, g1);
    }
    {
        const float4* g = img + (size_t)a1 * ROW_F4;
        float4 g0 = g[t], g1 = g[t + THREADS];
        acc[5] = dot4(tv0, g0) + dot4(tv1, g1);
        acc[6] = dot4(g0, g0) + dot4(g1, g1);
    }
    {   // text candidates (anchor = img) -> i2t side
        const float4* g = txt + (size_t)b0 * ROW_F4;
        float4 g0 = g[t], g1 = g[t + THREADS];
        acc[7] = dot4(iv0, g0) + dot4(iv1, g1);
        acc[8] = dot4(g0, g0) + dot4(g1, g1);
    }
    {
        const float4* g = txt + (size_t)b1 * ROW_F4;
        float4 g0 = g[t], g1 = g[t + THREADS];
        acc[9]  = dot4(iv0, g0) + dot4(iv1, g1);
        acc[10] = dot4(g0, g0) + dot4(g1, g1);
    }

    #pragma unroll
    for (int k = 0; k < 11; k++) {
        float v = acc[k];
        #pragma unroll
        for (int off = 16; off > 0; off >>= 1)
            v += __shfl_xor_sync(0xFFFFFFFFu, v, off);
        acc[k] = v;
    }

    __shared__ float s[THREADS / 32][11];
    const int lane = t & 31, warp = t >> 5;
    if (lane == 0) {
        #pragma unroll
        for (int k = 0; k < 11; k++) s[warp][k] = acc[k];
    }
    __syncthreads();

    if (t == 0) {
        float r[11];
        #pragma unroll
        for (int k = 0; k < 11; k++) {
            float v = 0.f;
            #pragma unroll
            for (int w = 0; w < THREADS / 32; w++) v += s[w][k];
            r[k] = v;
        }

        const float n_i = sqrtf(r[0]);
        const float n_t = sqrtf(r[1]);
        const float prod = n_i * n_t;
        const float pos_dist = 1.0f - r[2] / fmaxf(prod, EPSV);
        const float cosv = r[2] / prod;

        const float dA0 = 1.0f - r[3] / fmaxf(n_t * sqrtf(r[4]), EPSV);
        const float dA1 = 1.0f - r[5] / fmaxf(n_t * sqrtf(r[6]), EPSV);
        const float t2i_neg = (dA1 <= dA0) ? dA1 : dA0;

        const float dB0 = 1.0f - r[7] / fmaxf(n_i * sqrtf(r[8]), EPSV);
        const float dB1 = 1.0f - r[9] / fmaxf(n_i * sqrtf(r[10]), EPSV);
        const float i2t_neg = (dB1 <= dB0) ? dB1 : dB0;

        const float i2t_loss = fmaxf(pos_dist - i2t_neg + MARGINV, 0.0f);
        const float t2i_loss = fmaxf(pos_dist - t2i_neg + MARGINV, 0.0f);

        out[1 + row]         = cosv;   // i2t_cosine
        out[1 + BATCH + row] = cosv;   // t2i_cosine (same symmetric formula)
        g_loss[row] = make_float2(i2t_loss, t2i_loss);
    }
}

__global__ __launch_bounds__(1024)
void contrastive_reduce(float* __restrict__ out) {
    const int t = threadIdx.x;
    float si = 0.f, st = 0.f;
    for (int i = t; i < BATCH; i += 1024) {
        float2 v = g_loss[i];
        si += v.x;
        st += v.y;
    }
    __shared__ float ssi[32], sst[32];
    #pragma unroll
    for (int off = 16; off > 0; off >>= 1) {
        si += __shfl_xor_sync(0xFFFFFFFFu, si, off);
        st += __shfl_xor_sync(0xFFFFFFFFu, st, off);
    }
    const int lane = t & 31, warp = t >> 5;
    if (lane == 0) { ssi[warp] = si; sst[warp] = st; }
    __syncthreads();
    if (t == 0) {
        float a = 0.f, b = 0.f;
        #pragma unroll
        for (int w = 0; w < 32; w++) { a += ssi[w]; b += sst[w]; }
        out[0] = a / (float)BATCH + b / (float)BATCH;
    }
}

extern "C" void kernel_launch(void* const* d_in, const int* in_sizes, int n_in,
                              void* d_out, int out_size) {
    const float4* img = (const float4*)d_in[0];
    const float4* txt = (const float4*)d_in[1];
    // d_in[2] = labels (unused), d_in[3] = locations (unused)
    const void* cand_img = d_in[4];
    const void* cand_txt = d_in[5];
    float* out = (float*)d_out;

    detect_dtype<<<1, 1024>>>((const unsigned*)cand_img, (const unsigned*)cand_txt);
    contrastive_main<<<BATCH, THREADS>>>(img, txt, cand_img, cand_txt, out);
    contrastive_reduce<<<1, 1024>>>(out);
}